// round 2
// baseline (speedup 1.0000x reference)
#include <cuda_runtime.h>
#include <cuda_bf16.h>

#define MODIFIER_COL 11
#define OWNER_COL    24
#define MAXG         8192
#define F_DIM        128

// Persistent scratch (no cudaMalloc allowed). Zero-initialized at load;
// finalize_kernel resets the used range to zero after each consumption, so
// every graph replay starts from a clean state (deterministic).
__device__ float g_cnt[MAXG];
__device__ float g_s0[MAXG];
__device__ float g_s1[MAXG];

// Segmented warp reduction over sorted keys, then one atomicAdd per
// (warp, segment-head). batch is sorted, so equal keys occupy contiguous
// lanes; the shfl_down tree below is the standard sorted-key segscan.
__global__ __launch_bounds__(256) void reduce_kernel(
    const float* __restrict__ nf,
    const int* __restrict__ batch,   // JAX x64 disabled => int64 becomes int32
    int N)
{
    int i    = blockIdx.x * blockDim.x + threadIdx.x;
    int lane = threadIdx.x & 31;

    int   g  = -1;
    float c  = 0.f, v0 = 0.f, v1 = 0.f;
    if (i < N) {
        g  = batch[i];
        const float* row = nf + (size_t)i * F_DIM;
        v0 = __ldg(row + MODIFIER_COL);
        v1 = __ldg(row + OWNER_COL);
        c  = 1.f;
    }

    // Down-sweep segmented reduction: lane L accumulates lanes of its own key
    // to its right. Valid because keys are non-decreasing across lanes.
    #pragma unroll
    for (int d = 1; d < 32; d <<= 1) {
        int   go = __shfl_down_sync(0xffffffffu, g,  d);
        float co = __shfl_down_sync(0xffffffffu, c,  d);
        float a0 = __shfl_down_sync(0xffffffffu, v0, d);
        float a1 = __shfl_down_sync(0xffffffffu, v1, d);
        if (lane + d < 32 && go == g) { c += co; v0 += a0; v1 += a1; }
    }

    int  gprev = __shfl_up_sync(0xffffffffu, g, 1);
    bool head  = (lane == 0) || (gprev != g);
    if (head && g >= 0 && g < MAXG) {      // bounds guard: never fault
        atomicAdd(&g_cnt[g], c);
        atomicAdd(&g_s0[g],  v0);
        atomicAdd(&g_s1[g],  v1);
    }
}

// One thread per graph: mean -> (1 - mean) -> 2->32 relu -> 32->1 sigmoid.
// Also RESETS the accumulators so the next graph replay starts from zero.
__global__ __launch_bounds__(256) void finalize_kernel(
    const float* __restrict__ W1,   // [32, 2] row-major
    const float* __restrict__ b1,   // [32]
    const float* __restrict__ W2,   // [1, 32]
    const float* __restrict__ b2,   // [1]
    float* __restrict__ out,
    int G)
{
    int g = blockIdx.x * blockDim.x + threadIdx.x;
    if (g >= G) return;

    float c  = g_cnt[g];
    float s0 = g_s0[g];
    float s1 = g_s1[g];
    // reset for next replay (next launch's reduce runs after this in stream
    // order, so no race)
    g_cnt[g] = 0.f;
    g_s0[g]  = 0.f;
    g_s1[g]  = 0.f;

    float denom = fmaxf(c, 1.f);
    float a0 = 1.f - s0 / denom;
    float a1 = 1.f - s1 / denom;

    float acc = __ldg(b2);
    #pragma unroll
    for (int j = 0; j < 32; ++j) {
        float h = fmaf(a0, __ldg(W1 + 2 * j),
                  fmaf(a1, __ldg(W1 + 2 * j + 1), __ldg(b1 + j)));
        h   = fmaxf(h, 0.f);
        acc = fmaf(__ldg(W2 + j), h, acc);
    }
    float score = 1.f / (1.f + __expf(-acc));
    out[g] = (c > 0.f) ? score : 0.f;
}

extern "C" void kernel_launch(void* const* d_in, const int* in_sizes, int n_in,
                              void* d_out, int out_size)
{
    // metadata order: node_features, batch, graph_embedding, W1, b1, W2, b2, [num_graphs]
    const float* nf    = (const float*)d_in[0];
    const int*   batch = (const int*)d_in[1];
    // d_in[2] = graph_embedding: only used to derive G (it is dead in the math)
    const float* W1    = (const float*)d_in[3];
    const float* b1    = (const float*)d_in[4];
    const float* W2    = (const float*)d_in[5];
    const float* b2    = (const float*)d_in[6];
    float*       out   = (float*)d_out;

    int N = in_sizes[1];               // number of nodes
    int G = in_sizes[2] / F_DIM;       // graphs from graph_embedding shape
    if (G <= 0 || G > MAXG) G = out_size;  // fallback: out has one score per graph

    int rb = (N + 255) / 256;
    reduce_kernel<<<rb, 256>>>(nf, batch, N);

    int fb = (G + 255) / 256;
    finalize_kernel<<<fb, 256>>>(W1, b1, W2, b2, out, G);
}